// round 1
// baseline (speedup 1.0000x reference)
#include <cuda_runtime.h>
#include <cuda_bf16.h>
#include <math.h>

#define D 128
#define NMAX 100000

// Scratch (static __device__ — no allocations allowed)
__device__ float g_agg[(size_t)NMAX * D];   // 51.2 MB
__device__ float g_deg[NMAX];
__device__ float g_h[(size_t)NMAX * D];     // 51.2 MB

__device__ __forceinline__ void red_add_v4(float* p, float4 v) {
    asm volatile("red.global.add.v4.f32 [%0], {%1,%2,%3,%4};"
                 :: "l"(p), "f"(v.x), "f"(v.y), "f"(v.z), "f"(v.w) : "memory");
}

__device__ __forceinline__ float tanh_approx(float x) {
    float y;
    asm("tanh.approx.f32 %0, %1;" : "=f"(y) : "f"(x));
    return y;
}

// ---------------------------------------------------------------------------
// Zero agg + deg
// ---------------------------------------------------------------------------
__global__ void zero_kernel(int Nn) {
    size_t total4 = (size_t)Nn * D / 4;
    size_t stride = (size_t)gridDim.x * blockDim.x;
    for (size_t i = (size_t)blockIdx.x * blockDim.x + threadIdx.x; i < total4; i += stride)
        reinterpret_cast<float4*>(g_agg)[i] = make_float4(0.f, 0.f, 0.f, 0.f);
    for (size_t i = (size_t)blockIdx.x * blockDim.x + threadIdx.x; i < (size_t)Nn; i += stride)
        g_deg[i] = 0.f;
}

// ---------------------------------------------------------------------------
// Conv scatter: one warp per edge.  agg[dst] += x[src] * rel[type]; deg[dst]++
// ---------------------------------------------------------------------------
__global__ __launch_bounds__(256)
void conv_scatter(const float* __restrict__ x,
                  const float* __restrict__ rel,
                  const int* __restrict__ ei,   // [2, E] flattened
                  const int* __restrict__ et,
                  int E)
{
    int lane = threadIdx.x & 31;
    int warp = blockIdx.x * (blockDim.x >> 5) + (threadIdx.x >> 5);
    int nwarps = gridDim.x * (blockDim.x >> 5);
    for (int e = warp; e < E; e += nwarps) {
        int src = ei[e];
        int dst = ei[E + e];
        int t   = et[e];
        float4 xv = reinterpret_cast<const float4*>(x   + (size_t)src * D)[lane];
        float4 rv = reinterpret_cast<const float4*>(rel + (size_t)t   * D)[lane];
        float4 m = make_float4(xv.x * rv.x, xv.y * rv.y, xv.z * rv.z, xv.w * rv.w);
        red_add_v4(g_agg + (size_t)dst * D + lane * 4, m);
        if (lane == 0) atomicAdd(&g_deg[dst], 1.0f);
    }
}

// ---------------------------------------------------------------------------
// Jump scatter: out[dst] += jw * ew[e] * emb[src]
// ---------------------------------------------------------------------------
__global__ __launch_bounds__(256)
void jump_scatter(const float* __restrict__ emb,
                  const float* __restrict__ ew,
                  const float* __restrict__ jwp,
                  const int* __restrict__ ej,
                  float* __restrict__ out, int EJ)
{
    float jw = __ldg(jwp);
    int lane = threadIdx.x & 31;
    int warp = blockIdx.x * (blockDim.x >> 5) + (threadIdx.x >> 5);
    int nwarps = gridDim.x * (blockDim.x >> 5);
    for (int e = warp; e < EJ; e += nwarps) {
        int src = ej[e];
        int dst = ej[EJ + e];
        float w = jw * ew[e];
        float4 v = reinterpret_cast<const float4*>(emb + (size_t)src * D)[lane];
        v.x *= w; v.y *= w; v.z *= w; v.w *= w;
        red_add_v4(out + (size_t)dst * D + lane * 4, v);
    }
}

// ---------------------------------------------------------------------------
// Fused GEMM + epilogue:
//   out = x + res * tanh( (agg/deg) @ Wa + x @ Wx )
// A = [agg_norm | x]  (N x 256),  B = [[Wa],[Wx]]  (256 x 128)
// bf16 hi/lo split, 3 passes (AhBh + AlBh + AhBl) -> ~fp32 accuracy.
// Block = 64 rows x 128 cols, 8 warps (4 m-tiles x 2 n-halves).
// Persistent blocks: weights staged in smem once per block.
// ---------------------------------------------------------------------------
#define BM 64
#define KK (2 * D)          // 256
#define AS (KK + 8)         // 264 (pad: conflict-free ldmatrix)
#define BS (D + 8)          // 136
#define SMEM_BYTES ((2 * BM * AS + 2 * KK * BS) * 2)   // 206848

__global__ __launch_bounds__(256, 1)
void fused_gemm(const float* __restrict__ x,
                const float* __restrict__ Wa,
                const float* __restrict__ Wx,
                const float* __restrict__ resp,
                float* __restrict__ out,
                int Nn, int ntiles)
{
    extern __shared__ __nv_bfloat16 sm[];
    __nv_bfloat16* Ah = sm;
    __nv_bfloat16* Al = Ah + BM * AS;
    __nv_bfloat16* Bh = Al + BM * AS;
    __nv_bfloat16* Bl = Bh + KK * BS;

    int tid  = threadIdx.x;
    int lane = tid & 31;
    int wid  = tid >> 5;
    int wm   = wid & 3;     // m-tile (16 rows each)
    int wn   = wid >> 2;    // n-half (64 cols each)

    // ---- stage weights (once per block), hi/lo bf16 ----
    for (int idx = tid; idx < KK * D / 4; idx += 256) {
        int k  = idx >> 5;             // 0..255
        int c4 = (idx & 31) * 4;
        const float* src = (k < D) ? (Wa + (size_t)k * D) : (Wx + (size_t)(k - D) * D);
        float4 v = *reinterpret_cast<const float4*>(src + c4);
        float f[4] = {v.x, v.y, v.z, v.w};
        #pragma unroll
        for (int j = 0; j < 4; j++) {
            __nv_bfloat16 h = __float2bfloat16(f[j]);
            Bh[k * BS + c4 + j] = h;
            Bl[k * BS + c4 + j] = __float2bfloat16(f[j] - __bfloat162float(h));
        }
    }

    float resv = __ldg(resp);

    for (int tile = blockIdx.x; tile < ntiles; tile += gridDim.x) {
        int row0 = tile * BM;
        __syncthreads();   // protects smem A reuse (and B on first iter)

        // ---- stage A tile: [agg/deg | x], hi/lo bf16 ----
        for (int idx = tid; idx < BM * KK / 4; idx += 256) {
            int r  = idx >> 6;             // 0..63
            int c4 = (idx & 63) * 4;       // 0..252
            int row = row0 + r;
            float4 v = make_float4(0.f, 0.f, 0.f, 0.f);
            if (row < Nn) {
                if (c4 < D) {
                    v = *reinterpret_cast<const float4*>(g_agg + (size_t)row * D + c4);
                    float id = 1.0f / fmaxf(g_deg[row], 1.0f);
                    v.x *= id; v.y *= id; v.z *= id; v.w *= id;
                } else {
                    v = *reinterpret_cast<const float4*>(x + (size_t)row * D + (c4 - D));
                }
            }
            float f[4] = {v.x, v.y, v.z, v.w};
            #pragma unroll
            for (int j = 0; j < 4; j++) {
                __nv_bfloat16 h = __float2bfloat16(f[j]);
                Ah[r * AS + c4 + j] = h;
                Al[r * AS + c4 + j] = __float2bfloat16(f[j] - __bfloat162float(h));
            }
        }
        __syncthreads();

        float acc[8][4];
        #pragma unroll
        for (int j = 0; j < 8; j++)
            #pragma unroll
            for (int q = 0; q < 4; q++) acc[j][q] = 0.f;

        // fragment addressing (canonical ldmatrix.x4 lane mapping)
        int arow = wm * 16 + (lane & 7) + ((lane >> 3) & 1) * 8;
        int acol = ((lane >> 4) & 1) * 8;
        int brow = (lane & 7) + ((lane >> 3) & 1) * 8;
        int bcol = wn * 64 + ((lane >> 4) & 1) * 8;

        #pragma unroll
        for (int pass = 0; pass < 3; pass++) {
            const __nv_bfloat16* As = (pass == 1) ? Al : Ah;
            const __nv_bfloat16* Bs = (pass == 2) ? Bl : Bh;
            #pragma unroll
            for (int kk = 0; kk < KK; kk += 16) {
                unsigned a0, a1, a2, a3;
                {
                    unsigned ad = (unsigned)__cvta_generic_to_shared(
                        &As[(size_t)arow * AS + kk + acol]);
                    asm volatile(
                        "ldmatrix.sync.aligned.m8n8.x4.shared.b16 {%0,%1,%2,%3}, [%4];"
                        : "=r"(a0), "=r"(a1), "=r"(a2), "=r"(a3) : "r"(ad));
                }
                #pragma unroll
                for (int nt = 0; nt < 4; nt++) {
                    unsigned b0, b1, b2, b3;
                    unsigned bd = (unsigned)__cvta_generic_to_shared(
                        &Bs[(size_t)(kk + brow) * BS + bcol + nt * 16]);
                    asm volatile(
                        "ldmatrix.sync.aligned.m8n8.x4.trans.shared.b16 {%0,%1,%2,%3}, [%4];"
                        : "=r"(b0), "=r"(b1), "=r"(b2), "=r"(b3) : "r"(bd));
                    asm volatile(
                        "mma.sync.aligned.m16n8k16.row.col.f32.bf16.bf16.f32 "
                        "{%0,%1,%2,%3}, {%4,%5,%6,%7}, {%8,%9}, {%0,%1,%2,%3};"
                        : "+f"(acc[nt*2][0]), "+f"(acc[nt*2][1]),
                          "+f"(acc[nt*2][2]), "+f"(acc[nt*2][3])
                        : "r"(a0), "r"(a1), "r"(a2), "r"(a3), "r"(b0), "r"(b1));
                    asm volatile(
                        "mma.sync.aligned.m16n8k16.row.col.f32.bf16.bf16.f32 "
                        "{%0,%1,%2,%3}, {%4,%5,%6,%7}, {%8,%9}, {%0,%1,%2,%3};"
                        : "+f"(acc[nt*2+1][0]), "+f"(acc[nt*2+1][1]),
                          "+f"(acc[nt*2+1][2]), "+f"(acc[nt*2+1][3])
                        : "r"(a0), "r"(a1), "r"(a2), "r"(a3), "r"(b2), "r"(b3));
                }
            }
        }

        // ---- epilogue: out = x + res * tanh(acc) ----
        int g = lane >> 2;
        int cbase = wn * 64 + (lane & 3) * 2;
        int r0 = row0 + wm * 16 + g;
        int r1 = r0 + 8;
        #pragma unroll
        for (int j = 0; j < 8; j++) {
            int col = cbase + j * 8;
            if (r0 < Nn) {
                float2 xv = *reinterpret_cast<const float2*>(x + (size_t)r0 * D + col);
                float2 o;
                o.x = xv.x + resv * tanh_approx(acc[j][0]);
                o.y = xv.y + resv * tanh_approx(acc[j][1]);
                *reinterpret_cast<float2*>(out + (size_t)r0 * D + col) = o;
            }
            if (r1 < Nn) {
                float2 xv = *reinterpret_cast<const float2*>(x + (size_t)r1 * D + col);
                float2 o;
                o.x = xv.x + resv * tanh_approx(acc[j][2]);
                o.y = xv.y + resv * tanh_approx(acc[j][3]);
                *reinterpret_cast<float2*>(out + (size_t)r1 * D + col) = o;
            }
        }
    }
}

// ---------------------------------------------------------------------------
extern "C" void kernel_launch(void* const* d_in, const int* in_sizes, int n_in,
                              void* d_out, int out_size)
{
    const float* emb    = (const float*)d_in[0];
    const float* change = (const float*)d_in[1];
    const float* W1     = (const float*)d_in[2];
    const float* Wl1    = (const float*)d_in[3];
    const float* rel1   = (const float*)d_in[4];
    const float* W2     = (const float*)d_in[5];
    const float* Wl2    = (const float*)d_in[6];
    const float* rel2   = (const float*)d_in[7];
    const float* res    = (const float*)d_in[8];
    const float* jw     = (const float*)d_in[9];
    const float* ewj    = (const float*)d_in[10];
    const int*   ei     = (const int*)d_in[11];
    const int*   et     = (const int*)d_in[12];
    const int*   ej     = (const int*)d_in[13];

    int Nn = in_sizes[0] / D;
    int E  = in_sizes[12];
    int EJ = in_sizes[10];
    int ntiles = (Nn + BM - 1) / BM;

    float* out_change = (float*)d_out;
    float* out_dch    = (float*)d_out + (size_t)Nn * D;

    void* hp = nullptr;
    cudaGetSymbolAddress(&hp, g_h);
    float* hbuf = (float*)hp;

    cudaFuncSetAttribute(fused_gemm, cudaFuncAttributeMaxDynamicSharedMemorySize,
                         SMEM_BYTES);

    // change passthrough (independent)
    cudaMemcpyAsync(out_change, change, (size_t)Nn * D * sizeof(float),
                    cudaMemcpyDeviceToDevice, 0);

    // Layer 1
    zero_kernel<<<2048, 256>>>(Nn);
    conv_scatter<<<4736, 256>>>(emb, rel1, ei, et, E);
    fused_gemm<<<152, 256, SMEM_BYTES>>>(emb, W1, Wl1, res, hbuf, Nn, ntiles);

    // Layer 2
    zero_kernel<<<2048, 256>>>(Nn);
    conv_scatter<<<4736, 256>>>(hbuf, rel2, ei, et, E);
    fused_gemm<<<152, 256, SMEM_BYTES>>>(hbuf, W2, Wl2, res, out_dch, Nn, ntiles);

    // Jump diffusion (accumulates onto dchange)
    jump_scatter<<<2368, 256>>>(emb, ewj, jw, ej, out_dch, EJ);
}